// round 3
// baseline (speedup 1.0000x reference)
#include <cuda_runtime.h>
#include <math.h>

#define BSZ    64
#define SEQ    512
#define DIM    768
#define NSPANS 1280
#define LMAX   5
#define H      200
#define G4     800     // 4*H
#define NENT   16
#define EMB    400     // 2*H
#define MTOT   (NSPANS * LMAX)

// ---------------- scratch (static device globals; no allocation) -------------
__device__ float g_y[2 * MTOT * G4];            // xg for both dirs (~41 MB)
__device__ float g_wt[2 * H * G4];              // W_hh transposed: [dir][k][g]
__device__ float g_feats[NSPANS * EMB];         // [span][sum_f | sum_b]
__device__ int   g_rowSrc[MTOT];                // compacted valid row -> m
__device__ int   g_cnt;                         // number of valid rows

// ---------------- f32x2 packed helpers (sm_103a) -----------------------------
typedef unsigned long long ull;

__device__ __forceinline__ ull ffma2(ull a, ull b, ull c) {
    ull d;
    asm("fma.rn.f32x2 %0, %1, %2, %3;" : "=l"(d) : "l"(a), "l"(b), "l"(c));
    return d;
}
__device__ __forceinline__ ull pack2(float x) {
    ull r;
    asm("mov.b64 %0, {%1, %1};" : "=l"(r) : "f"(x));
    return r;
}
__device__ __forceinline__ void unpack2(ull v, float& lo, float& hi) {
    asm("mov.b64 {%0, %1}, %2;" : "=f"(lo), "=f"(hi) : "l"(v));
}

// ---------------- kernel 0: transpose W_hh [800,200] -> [200,800] ------------
// Also zeroes the compaction counter (runs before compact_rows in stream).
__global__ void transpose_whh(const float* __restrict__ Wf,
                              const float* __restrict__ Wb) {
    if (blockIdx.x == 0 && blockIdx.y == 0 && blockIdx.z == 0 &&
        threadIdx.x == 0 && threadIdx.y == 0)
        g_cnt = 0;
    __shared__ float tile[32][33];
    int dir = blockIdx.z;
    const float* W = dir ? Wb : Wf;
    int k0 = blockIdx.x * 32;      // k (0..199)
    int g0 = blockIdx.y * 32;      // g (0..799)
    int tx = threadIdx.x, ty = threadIdx.y;   // 32 x 8
    #pragma unroll
    for (int i = 0; i < 32; i += 8) {
        int g = g0 + ty + i, k = k0 + tx;
        tile[ty + i][tx] = (g < G4 && k < H) ? W[g * H + k] : 0.f;
    }
    __syncthreads();
    #pragma unroll
    for (int i = 0; i < 32; i += 8) {
        int k = k0 + ty + i, g = g0 + tx;
        if (k < H && g < G4)
            g_wt[dir * (H * G4) + k * G4 + g] = tile[tx][ty + i];
    }
}

// ---------------- kernel 0b: build valid-row list ----------------------------
// One thread per span grabs span_len consecutive slots. Slot ORDER is
// atomic-dependent but the final output is order-independent (pure scatter).
__global__ void compact_rows(const int* __restrict__ span_len) {
    int n = blockIdx.x * blockDim.x + threadIdx.x;
    if (n < NSPANS) {
        int len = span_len[n];
        int r = atomicAdd(&g_cnt, len);
        for (int l = 0; l < len; l++)
            g_rowSrc[r + l] = n * LMAX + l;
    }
}

// ---------------- kernel 1: gathered input GEMM over valid rows --------------
// y[dir][m][g] = sum_d x[m][d] * W_ih[dir][g][d] + b_ih[g] + b_hh[g]
// Only valid rows (l < span_len) are computed; masked rows are never read
// downstream (the recurrence substitutes the bias).
// Double-buffered smem pipeline: stage tile i+1 while computing tile i.
#define BM 128
#define BN 64
#define BK 16
#define NKI (DIM / BK)

__global__ __launch_bounds__(256) void input_gemm(
    const float* __restrict__ hidden,
    const int*   __restrict__ tok_idx,
    const int*   __restrict__ span_batch,
    const float* __restrict__ Wf, const float* __restrict__ bihf, const float* __restrict__ bhhf,
    const float* __restrict__ Wb, const float* __restrict__ bihb, const float* __restrict__ bhhb)
{
    int Mv = g_cnt;                       // valid row count (set by compact_rows)
    int m0 = blockIdx.x * BM;
    if (m0 >= Mv) return;

    int dir = blockIdx.z;
    const float* W   = dir ? Wb   : Wf;
    const float* bih = dir ? bihb : bihf;
    const float* bhh = dir ? bhhb : bhhf;

    __shared__ __align__(16) float As[2][BK][BM + 4];
    __shared__ __align__(16) float Bs[2][BK][BN + 4];
    __shared__ int rowBase[BM];
    __shared__ int rowDst[BM];

    int tid = threadIdx.x;
    int g0 = blockIdx.y * BN;

    if (tid < BM) {
        int r = m0 + tid;
        int base = -1, msrc = -1;
        if (r < Mv) {
            msrc = g_rowSrc[r];
            int n = msrc / LMAX, l = msrc % LMAX;
            base = (span_batch[n] * SEQ + tok_idx[n * LMAX + l]) * DIM;
        }
        rowBase[tid] = base;
        rowDst[tid]  = msrc;
    }
    __syncthreads();

    // Per-thread staging coordinates (constant across iterations)
    const int aM0 = tid >> 2,        aKq0 = tid & 3;          // A load 0
    const int aM1 = (tid + 256) >> 2, aKq1 = tid & 3;         // A load 1
    const int bG  = tid >> 2,        bKq  = tid & 3;          // B load
    const int aBase0 = rowBase[aM0];
    const int aBase1 = rowBase[aM1];
    const int bOk = (g0 + bG) < G4;
    const float* bSrc = W + (size_t)(g0 + bG) * DIM + bKq * 4;

    // stage tile (k0) into buffer buf
    auto stage = [&](int buf, int k0) {
        float4 v0 = make_float4(0.f, 0.f, 0.f, 0.f);
        float4 v1 = v0, vb = v0;
        if (aBase0 >= 0) v0 = *(const float4*)(hidden + aBase0 + k0 + aKq0 * 4);
        if (aBase1 >= 0) v1 = *(const float4*)(hidden + aBase1 + k0 + aKq1 * 4);
        if (bOk)         vb = *(const float4*)(bSrc + k0);
        As[buf][aKq0 * 4 + 0][aM0] = v0.x; As[buf][aKq0 * 4 + 1][aM0] = v0.y;
        As[buf][aKq0 * 4 + 2][aM0] = v0.z; As[buf][aKq0 * 4 + 3][aM0] = v0.w;
        As[buf][aKq1 * 4 + 0][aM1] = v1.x; As[buf][aKq1 * 4 + 1][aM1] = v1.y;
        As[buf][aKq1 * 4 + 2][aM1] = v1.z; As[buf][aKq1 * 4 + 3][aM1] = v1.w;
        Bs[buf][bKq * 4 + 0][bG] = vb.x; Bs[buf][bKq * 4 + 1][bG] = vb.y;
        Bs[buf][bKq * 4 + 2][bG] = vb.z; Bs[buf][bKq * 4 + 3][bG] = vb.w;
    };

    // 8 rows x 4 cols per thread, rows as 4 packed f32x2 pairs
    ull acc2[4][4];
    #pragma unroll
    for (int p = 0; p < 4; p++)
        #pragma unroll
        for (int j = 0; j < 4; j++) acc2[p][j] = 0ull;

    int ty = tid >> 4;   // 0..15 -> 8 rows each
    int tx = tid & 15;   // 0..15 -> 4 cols each

    stage(0, 0);
    __syncthreads();

    int cur = 0;
    for (int it = 0; it < NKI; it++) {
        if (it + 1 < NKI)
            stage(cur ^ 1, (it + 1) * BK);     // overlap with compute below

        #pragma unroll
        for (int k = 0; k < BK; k++) {
            ulonglong2 av0 = *(const ulonglong2*)(&As[cur][k][ty * 8]);
            ulonglong2 av1 = *(const ulonglong2*)(&As[cur][k][ty * 8 + 4]);
            ull ap[4] = {av0.x, av0.y, av1.x, av1.y};
            float4 bv = *(const float4*)(&Bs[cur][k][tx * 4]);
            ull bb[4] = {pack2(bv.x), pack2(bv.y), pack2(bv.z), pack2(bv.w)};
            #pragma unroll
            for (int p = 0; p < 4; p++)
                #pragma unroll
                for (int j = 0; j < 4; j++)
                    acc2[p][j] = ffma2(ap[p], bb[j], acc2[p][j]);
        }
        __syncthreads();
        cur ^= 1;
    }

    int gbase = g0 + tx * 4;
    if (gbase < G4) {    // G4 % 4 == 0 -> whole float4 valid or not
        float bias[4];
        #pragma unroll
        for (int j = 0; j < 4; j++) bias[j] = bih[gbase + j] + bhh[gbase + j];
        #pragma unroll
        for (int p = 0; p < 4; p++) {
            float lo[4], hi[4];
            #pragma unroll
            for (int j = 0; j < 4; j++) unpack2(acc2[p][j], lo[j], hi[j]);
            int d0 = rowDst[ty * 8 + 2 * p];
            int d1 = rowDst[ty * 8 + 2 * p + 1];
            if (d0 >= 0)
                *(float4*)(g_y + ((size_t)dir * MTOT + d0) * G4 + gbase) =
                    make_float4(lo[0] + bias[0], lo[1] + bias[1],
                                lo[2] + bias[2], lo[3] + bias[3]);
            if (d1 >= 0)
                *(float4*)(g_y + ((size_t)dir * MTOT + d1) * G4 + gbase) =
                    make_float4(hi[0] + bias[0], hi[1] + bias[1],
                                hi[2] + bias[2], hi[3] + bias[3]);
        }
    }
}

// ---------------- kernel 2: batched LSTM recurrence --------------------------
// One block = 16 spans x 1 direction. Thread j (<200) owns h column j.
// Masked forward steps (t >= len) use the bias directly (their xg row was
// never computed by the compacted GEMM). Backward steps t >= len read row 0,
// which is always valid (len >= 1) — matches the reference's clipped rev_idx.
#define GSP 16

__global__ __launch_bounds__(256, 1) void lstm_rec(
    const int* __restrict__ span_len,
    const float* __restrict__ bihf, const float* __restrict__ bhhf,
    const float* __restrict__ bihb, const float* __restrict__ bhhb)
{
    int dir = blockIdx.y;
    int s0  = blockIdx.x * GSP;
    int tid = threadIdx.x;

    __shared__ float hsm[GSP][H + 8];
    __shared__ int   len_s[GSP];

    if (tid < GSP) len_s[tid] = span_len[s0 + tid];
    for (int i = tid; i < GSP * (H + 8); i += 256) ((float*)hsm)[i] = 0.f;
    __syncthreads();

    const float* Wt  = g_wt + (size_t)dir * (H * G4);
    const float* bih = dir ? bihb : bihf;
    const float* bhh = dir ? bhhb : bhhf;
    const int j = tid;

    float bi0 = 0.f, bi1 = 0.f, bi2 = 0.f, bi3 = 0.f;
    if (tid < H) {
        bi0 = bih[j]         + bhh[j];
        bi1 = bih[H + j]     + bhh[H + j];
        bi2 = bih[2 * H + j] + bhh[2 * H + j];
        bi3 = bih[3 * H + j] + bhh[3 * H + j];
    }

    float c[GSP], sum[GSP], hn[GSP];
    #pragma unroll
    for (int s = 0; s < GSP; s++) { c[s] = 0.f; sum[s] = 0.f; hn[s] = 0.f; }

    for (int t = 0; t < LMAX; t++) {
        if (tid < H) {
            float a0[GSP], a1[GSP], a2[GSP], a3[GSP];
            #pragma unroll
            for (int s = 0; s < GSP; s++) {
                int len = len_s[s];
                if (dir == 0 && t >= len) {
                    a0[s] = bi0; a1[s] = bi1; a2[s] = bi2; a3[s] = bi3;
                } else {
                    int tl = (dir == 0) ? t : (len - 1 - t);
                    if (tl < 0) tl = 0;   // backward, t >= len -> row 0 (valid)
                    const float* yr = g_y +
                        (((size_t)dir * NSPANS + (s0 + s)) * LMAX + tl) * G4;
                    a0[s] = yr[j];
                    a1[s] = yr[H + j];
                    a2[s] = yr[2 * H + j];
                    a3[s] = yr[3 * H + j];
                }
            }
            #pragma unroll 2
            for (int k = 0; k < H; k++) {
                const float* wr = Wt + (size_t)k * G4;
                float w0 = wr[j], w1 = wr[H + j], w2 = wr[2 * H + j], w3 = wr[3 * H + j];
                #pragma unroll
                for (int s = 0; s < GSP; s++) {
                    float hk = hsm[s][k];
                    a0[s] += w0 * hk; a1[s] += w1 * hk;
                    a2[s] += w2 * hk; a3[s] += w3 * hk;
                }
            }
            #pragma unroll
            for (int s = 0; s < GSP; s++) {
                float ig = 1.f / (1.f + __expf(-a0[s]));
                float fg = 1.f / (1.f + __expf(-a1[s]));
                float gg = 1.f - 2.f / (1.f + __expf(2.f * a2[s]));   // tanh
                float og = 1.f / (1.f + __expf(-a3[s]));
                float cn = fg * c[s] + ig * gg;
                c[s] = cn;
                float hv = og * (1.f - 2.f / (1.f + __expf(2.f * cn)));
                hn[s] = hv;
                if (t < len_s[s]) sum[s] += hv;
            }
        }
        __syncthreads();
        if (tid < H) {
            #pragma unroll
            for (int s = 0; s < GSP; s++) hsm[s][j] = hn[s];
        }
        __syncthreads();
    }

    if (tid < H) {
        #pragma unroll
        for (int s = 0; s < GSP; s++)
            g_feats[(size_t)(s0 + s) * EMB + dir * H + j] = sum[s];
    }
}

// ---------------- kernel 3: logits = feats @ E^T -----------------------------
__global__ __launch_bounds__(256) void logits_kernel(
    const float* __restrict__ E, float* __restrict__ out)
{
    __shared__ float Es[NENT][EMB + 1];
    int tid = threadIdx.x;
    int s0  = blockIdx.x * 16;
    for (int i = tid; i < NENT * EMB; i += 256)
        Es[i / EMB][i % EMB] = E[i];
    __syncthreads();

    int sl = tid >> 4, e = tid & 15;
    const float* frow = g_feats + (size_t)(s0 + sl) * EMB;
    float acc = 0.f;
    #pragma unroll 4
    for (int k = 0; k < EMB; k++) acc += frow[k] * Es[e][k];
    out[(s0 + sl) * NENT + e] = acc;
}

// ---------------- launch -----------------------------------------------------
extern "C" void kernel_launch(void* const* d_in, const int* in_sizes, int n_in,
                              void* d_out, int out_size)
{
    const float* hidden = (const float*)d_in[0];
    const int*   tok    = (const int*)  d_in[1];
    const int*   slen   = (const int*)  d_in[2];
    const int*   sbatch = (const int*)  d_in[3];
    const float* Wihf   = (const float*)d_in[4];
    const float* Whhf   = (const float*)d_in[5];
    const float* bihf   = (const float*)d_in[6];
    const float* bhhf   = (const float*)d_in[7];
    const float* Wihb   = (const float*)d_in[8];
    const float* Whhb   = (const float*)d_in[9];
    const float* bihb   = (const float*)d_in[10];
    const float* bhhb   = (const float*)d_in[11];
    const float* E      = (const float*)d_in[12];
    float* out = (float*)d_out;

    transpose_whh<<<dim3(7, 25, 2), dim3(32, 8)>>>(Whhf, Whhb);   // also zeroes g_cnt
    compact_rows<<<(NSPANS + 255) / 256, 256>>>(slen);

    input_gemm<<<dim3(MTOT / BM, (G4 + BN - 1) / BN, 2), 256>>>(
        hidden, tok, sbatch, Wihf, bihf, bhhf, Wihb, bihb, bhhb);

    lstm_rec<<<dim3(NSPANS / GSP, 2), 256>>>(slen, bihf, bhhf, bihb, bhhb);

    logits_kernel<<<NSPANS / 16, 256>>>(E, out);
}

// round 4
// speedup vs baseline: 1.2074x; 1.2074x over previous
#include <cuda_runtime.h>
#include <math.h>

#define BSZ    64
#define SEQ    512
#define DIM    768
#define NSPANS 1280
#define LMAX   5
#define H      200
#define G4     800     // 4*H
#define NENT   16
#define EMB    400     // 2*H
#define MTOT   (NSPANS * LMAX)

// ---------------- scratch (static device globals; no allocation) -------------
__device__ float g_y[2 * MTOT * G4];            // xg for both dirs (~41 MB)
__device__ float g_wt[2 * H * G4];              // W_hh transposed: [dir][k][g]
__device__ float g_feats[NSPANS * EMB];         // [span][sum_f | sum_b]
__device__ int   g_rowSrc[MTOT];                // compacted valid row -> m
__device__ int   g_cnt;                         // number of valid rows

// ---------------- f32x2 packed helpers (sm_103a) -----------------------------
typedef unsigned long long ull;

__device__ __forceinline__ ull ffma2(ull a, ull b, ull c) {
    ull d;
    asm("fma.rn.f32x2 %0, %1, %2, %3;" : "=l"(d) : "l"(a), "l"(b), "l"(c));
    return d;
}
__device__ __forceinline__ ull pack2(float x) {
    ull r;
    asm("mov.b64 %0, {%1, %1};" : "=l"(r) : "f"(x));
    return r;
}
__device__ __forceinline__ ull packpair(float lo, float hi) {
    ull r;
    asm("mov.b64 %0, {%1, %2};" : "=l"(r) : "f"(lo), "f"(hi));
    return r;
}
__device__ __forceinline__ void unpack2(ull v, float& lo, float& hi) {
    asm("mov.b64 {%0, %1}, %2;" : "=f"(lo), "=f"(hi) : "l"(v));
}

// ---------------- kernel 0: transpose W_hh [800,200] -> [200,800] ------------
// Also zeroes the compaction counter (runs before compact_rows in stream).
__global__ void transpose_whh(const float* __restrict__ Wf,
                              const float* __restrict__ Wb) {
    if (blockIdx.x == 0 && blockIdx.y == 0 && blockIdx.z == 0 &&
        threadIdx.x == 0 && threadIdx.y == 0)
        g_cnt = 0;
    __shared__ float tile[32][33];
    int dir = blockIdx.z;
    const float* W = dir ? Wb : Wf;
    int k0 = blockIdx.x * 32;      // k (0..199)
    int g0 = blockIdx.y * 32;      // g (0..799)
    int tx = threadIdx.x, ty = threadIdx.y;   // 32 x 8
    #pragma unroll
    for (int i = 0; i < 32; i += 8) {
        int g = g0 + ty + i, k = k0 + tx;
        tile[ty + i][tx] = (g < G4 && k < H) ? W[g * H + k] : 0.f;
    }
    __syncthreads();
    #pragma unroll
    for (int i = 0; i < 32; i += 8) {
        int k = k0 + ty + i, g = g0 + tx;
        if (k < H && g < G4)
            g_wt[dir * (H * G4) + k * G4 + g] = tile[tx][ty + i];
    }
}

// ---------------- kernel 0b: build valid-row list ----------------------------
// One thread per span grabs span_len consecutive slots. Slot ORDER is
// atomic-dependent but the final output is order-independent (pure scatter).
__global__ void compact_rows(const int* __restrict__ span_len) {
    int n = blockIdx.x * blockDim.x + threadIdx.x;
    if (n < NSPANS) {
        int len = span_len[n];
        int r = atomicAdd(&g_cnt, len);
        for (int l = 0; l < len; l++)
            g_rowSrc[r + l] = n * LMAX + l;
    }
}

// ---------------- kernel 1: gathered input GEMM over valid rows --------------
// Double-buffered smem pipeline: stage tile i+1 while computing tile i.
#define BM 128
#define BN 64
#define BK 16
#define NKI (DIM / BK)

__global__ __launch_bounds__(256) void input_gemm(
    const float* __restrict__ hidden,
    const int*   __restrict__ tok_idx,
    const int*   __restrict__ span_batch,
    const float* __restrict__ Wf, const float* __restrict__ bihf, const float* __restrict__ bhhf,
    const float* __restrict__ Wb, const float* __restrict__ bihb, const float* __restrict__ bhhb)
{
    int Mv = g_cnt;                       // valid row count (set by compact_rows)
    int m0 = blockIdx.x * BM;
    if (m0 >= Mv) return;

    int dir = blockIdx.z;
    const float* W   = dir ? Wb   : Wf;
    const float* bih = dir ? bihb : bihf;
    const float* bhh = dir ? bhhb : bhhf;

    __shared__ __align__(16) float As[2][BK][BM + 4];
    __shared__ __align__(16) float Bs[2][BK][BN + 4];
    __shared__ int rowBase[BM];
    __shared__ int rowDst[BM];

    int tid = threadIdx.x;
    int g0 = blockIdx.y * BN;

    if (tid < BM) {
        int r = m0 + tid;
        int base = -1, msrc = -1;
        if (r < Mv) {
            msrc = g_rowSrc[r];
            int n = msrc / LMAX, l = msrc % LMAX;
            base = (span_batch[n] * SEQ + tok_idx[n * LMAX + l]) * DIM;
        }
        rowBase[tid] = base;
        rowDst[tid]  = msrc;
    }
    __syncthreads();

    const int aM0 = tid >> 2,         aKq0 = tid & 3;         // A load 0
    const int aM1 = (tid + 256) >> 2, aKq1 = tid & 3;         // A load 1
    const int bG  = tid >> 2,         bKq  = tid & 3;         // B load
    const int aBase0 = rowBase[aM0];
    const int aBase1 = rowBase[aM1];
    const int bOk = (g0 + bG) < G4;
    const float* bSrc = W + (size_t)(g0 + bG) * DIM + bKq * 4;

    auto stage = [&](int buf, int k0) {
        float4 v0 = make_float4(0.f, 0.f, 0.f, 0.f);
        float4 v1 = v0, vb = v0;
        if (aBase0 >= 0) v0 = *(const float4*)(hidden + aBase0 + k0 + aKq0 * 4);
        if (aBase1 >= 0) v1 = *(const float4*)(hidden + aBase1 + k0 + aKq1 * 4);
        if (bOk)         vb = *(const float4*)(bSrc + k0);
        As[buf][aKq0 * 4 + 0][aM0] = v0.x; As[buf][aKq0 * 4 + 1][aM0] = v0.y;
        As[buf][aKq0 * 4 + 2][aM0] = v0.z; As[buf][aKq0 * 4 + 3][aM0] = v0.w;
        As[buf][aKq1 * 4 + 0][aM1] = v1.x; As[buf][aKq1 * 4 + 1][aM1] = v1.y;
        As[buf][aKq1 * 4 + 2][aM1] = v1.z; As[buf][aKq1 * 4 + 3][aM1] = v1.w;
        Bs[buf][bKq * 4 + 0][bG] = vb.x; Bs[buf][bKq * 4 + 1][bG] = vb.y;
        Bs[buf][bKq * 4 + 2][bG] = vb.z; Bs[buf][bKq * 4 + 3][bG] = vb.w;
    };

    ull acc2[4][4];
    #pragma unroll
    for (int p = 0; p < 4; p++)
        #pragma unroll
        for (int j = 0; j < 4; j++) acc2[p][j] = 0ull;

    int ty = tid >> 4;   // 0..15 -> 8 rows each
    int tx = tid & 15;   // 0..15 -> 4 cols each

    stage(0, 0);
    __syncthreads();

    int cur = 0;
    for (int it = 0; it < NKI; it++) {
        if (it + 1 < NKI)
            stage(cur ^ 1, (it + 1) * BK);     // overlap with compute below

        #pragma unroll
        for (int k = 0; k < BK; k++) {
            ulonglong2 av0 = *(const ulonglong2*)(&As[cur][k][ty * 8]);
            ulonglong2 av1 = *(const ulonglong2*)(&As[cur][k][ty * 8 + 4]);
            ull ap[4] = {av0.x, av0.y, av1.x, av1.y};
            float4 bv = *(const float4*)(&Bs[cur][k][tx * 4]);
            ull bb[4] = {pack2(bv.x), pack2(bv.y), pack2(bv.z), pack2(bv.w)};
            #pragma unroll
            for (int p = 0; p < 4; p++)
                #pragma unroll
                for (int j = 0; j < 4; j++)
                    acc2[p][j] = ffma2(ap[p], bb[j], acc2[p][j]);
        }
        __syncthreads();
        cur ^= 1;
    }

    int gbase = g0 + tx * 4;
    if (gbase < G4) {
        float bias[4];
        #pragma unroll
        for (int j = 0; j < 4; j++) bias[j] = bih[gbase + j] + bhh[gbase + j];
        #pragma unroll
        for (int p = 0; p < 4; p++) {
            float lo[4], hi[4];
            #pragma unroll
            for (int j = 0; j < 4; j++) unpack2(acc2[p][j], lo[j], hi[j]);
            int d0 = rowDst[ty * 8 + 2 * p];
            int d1 = rowDst[ty * 8 + 2 * p + 1];
            if (d0 >= 0)
                *(float4*)(g_y + ((size_t)dir * MTOT + d0) * G4 + gbase) =
                    make_float4(lo[0] + bias[0], lo[1] + bias[1],
                                lo[2] + bias[2], lo[3] + bias[3]);
            if (d1 >= 0)
                *(float4*)(g_y + ((size_t)dir * MTOT + d1) * G4 + gbase) =
                    make_float4(hi[0] + bias[0], hi[1] + bias[1],
                                hi[2] + bias[2], hi[3] + bias[3]);
        }
    }
}

// ---------------- kernel 2: batched LSTM recurrence (rewritten) --------------
// GSP=8 spans/block, 224 threads (7 warps), thread j<200 owns hidden unit j.
// h stored transposed hsm[k][span] (pitch 10 -> aligned LDS.64 span-pairs,
// broadcast reads). Inner product uses packed fma.rn.f32x2 on span-pairs:
// per k-step: 4 coalesced LDG (W row), 4 LDS.64 (h pairs), 16 FFMA2.
#define GSP 8

__global__ __launch_bounds__(224) void lstm_rec(
    const int* __restrict__ span_len,
    const float* __restrict__ bihf, const float* __restrict__ bhhf,
    const float* __restrict__ bihb, const float* __restrict__ bhhb)
{
    int dir = blockIdx.y;
    int s0  = blockIdx.x * GSP;
    int tid = threadIdx.x;

    __shared__ float hsm[H][GSP + 2];     // [unit][span], pitch 10 floats
    __shared__ int   len_s[GSP];

    if (tid < GSP) len_s[tid] = span_len[s0 + tid];
    for (int i = tid; i < H * (GSP + 2); i += 224) ((float*)hsm)[i] = 0.f;
    __syncthreads();

    const float* Wt  = g_wt + (size_t)dir * (H * G4);
    const float* bih = dir ? bihb : bihf;
    const float* bhh = dir ? bhhb : bhhf;
    const int j = tid;

    float bi[4] = {0.f, 0.f, 0.f, 0.f};
    if (tid < H) {
        #pragma unroll
        for (int g = 0; g < 4; g++) bi[g] = bih[g * H + j] + bhh[g * H + j];
    }

    float c[GSP], sum[GSP], hn[GSP];
    #pragma unroll
    for (int s = 0; s < GSP; s++) { c[s] = 0.f; sum[s] = 0.f; hn[s] = 0.f; }

    for (int t = 0; t < LMAX; t++) {
        if (tid < H) {
            // gate accumulators: [gate][span-pair], init from xg (or bias)
            ull a2[4][4];
            #pragma unroll
            for (int p = 0; p < 4; p++) {
                float v[2][4];
                #pragma unroll
                for (int half = 0; half < 2; half++) {
                    int s = 2 * p + half;
                    int len = len_s[s];
                    if (dir == 0 && t >= len) {
                        #pragma unroll
                        for (int g = 0; g < 4; g++) v[half][g] = bi[g];
                    } else {
                        int tl = (dir == 0) ? t : (len - 1 - t);
                        if (tl < 0) tl = 0;   // backward, t>=len -> row 0 (valid)
                        const float* yr = g_y +
                            (((size_t)dir * NSPANS + (s0 + s)) * LMAX + tl) * G4;
                        #pragma unroll
                        for (int g = 0; g < 4; g++) v[half][g] = yr[g * H + j];
                    }
                }
                #pragma unroll
                for (int g = 0; g < 4; g++)
                    a2[g][p] = packpair(v[0][g], v[1][g]);
            }

            // h @ W_hh^T : K = 200
            #pragma unroll 2
            for (int k = 0; k < H; k++) {
                const float* wr = Wt + (size_t)k * G4;
                ull w[4];
                #pragma unroll
                for (int g = 0; g < 4; g++) w[g] = pack2(wr[g * H + j]);
                ull hp[4];
                #pragma unroll
                for (int p = 0; p < 4; p++)
                    hp[p] = *(const ull*)&hsm[k][2 * p];
                #pragma unroll
                for (int g = 0; g < 4; g++)
                    #pragma unroll
                    for (int p = 0; p < 4; p++)
                        a2[g][p] = ffma2(hp[p], w[g], a2[g][p]);
            }

            // nonlinearities (scalar per span)
            #pragma unroll
            for (int p = 0; p < 4; p++) {
                float ga[2][4];
                #pragma unroll
                for (int g = 0; g < 4; g++)
                    unpack2(a2[g][p], ga[0][g], ga[1][g]);
                #pragma unroll
                for (int half = 0; half < 2; half++) {
                    int s = 2 * p + half;
                    float ig = 1.f / (1.f + __expf(-ga[half][0]));
                    float fg = 1.f / (1.f + __expf(-ga[half][1]));
                    float gg = 1.f - 2.f / (1.f + __expf(2.f * ga[half][2]));  // tanh
                    float og = 1.f / (1.f + __expf(-ga[half][3]));
                    float cn = fg * c[s] + ig * gg;
                    c[s] = cn;
                    float hv = og * (1.f - 2.f / (1.f + __expf(2.f * cn)));
                    hn[s] = hv;
                    if (t < len_s[s]) sum[s] += hv;
                }
            }
        }
        __syncthreads();
        if (tid < H) {
            #pragma unroll
            for (int p = 0; p < 4; p++)
                *(float2*)&hsm[j][2 * p] = make_float2(hn[2 * p], hn[2 * p + 1]);
        }
        __syncthreads();
    }

    if (tid < H) {
        #pragma unroll
        for (int s = 0; s < GSP; s++)
            g_feats[(size_t)(s0 + s) * EMB + dir * H + j] = sum[s];
    }
}

// ---------------- kernel 3: logits = feats @ E^T -----------------------------
__global__ __launch_bounds__(256) void logits_kernel(
    const float* __restrict__ E, float* __restrict__ out)
{
    __shared__ float Es[NENT][EMB + 1];
    int tid = threadIdx.x;
    int s0  = blockIdx.x * 16;
    for (int i = tid; i < NENT * EMB; i += 256)
        Es[i / EMB][i % EMB] = E[i];
    __syncthreads();

    int sl = tid >> 4, e = tid & 15;
    const float* frow = g_feats + (size_t)(s0 + sl) * EMB;
    float acc = 0.f;
    #pragma unroll 4
    for (int k = 0; k < EMB; k++) acc += frow[k] * Es[e][k];
    out[(s0 + sl) * NENT + e] = acc;
}

// ---------------- launch -----------------------------------------------------
extern "C" void kernel_launch(void* const* d_in, const int* in_sizes, int n_in,
                              void* d_out, int out_size)
{
    const float* hidden = (const float*)d_in[0];
    const int*   tok    = (const int*)  d_in[1];
    const int*   slen   = (const int*)  d_in[2];
    const int*   sbatch = (const int*)  d_in[3];
    const float* Wihf   = (const float*)d_in[4];
    const float* Whhf   = (const float*)d_in[5];
    const float* bihf   = (const float*)d_in[6];
    const float* bhhf   = (const float*)d_in[7];
    const float* Wihb   = (const float*)d_in[8];
    const float* Whhb   = (const float*)d_in[9];
    const float* bihb   = (const float*)d_in[10];
    const float* bhhb   = (const float*)d_in[11];
    const float* E      = (const float*)d_in[12];
    float* out = (float*)d_out;

    transpose_whh<<<dim3(7, 25, 2), dim3(32, 8)>>>(Whhf, Whhb);   // also zeroes g_cnt
    compact_rows<<<(NSPANS + 255) / 256, 256>>>(slen);

    input_gemm<<<dim3(MTOT / BM, (G4 + BN - 1) / BN, 2), 256>>>(
        hidden, tok, sbatch, Wihf, bihf, bhhf, Wihb, bihb, bhhb);

    lstm_rec<<<dim3(NSPANS / GSP, 2), 224>>>(slen, bihf, bhhf, bihb, bhhb);

    logits_kernel<<<NSPANS / 16, 256>>>(E, out);
}

// round 6
// speedup vs baseline: 1.5797x; 1.3084x over previous
#include <cuda_runtime.h>
#include <math.h>

#define BSZ    64
#define SEQ    512
#define DIM    768
#define NSPANS 1280
#define LMAX   5
#define H      200
#define G4     800     // 4*H
#define NENT   16
#define EMB    400     // 2*H
#define MTOT   (NSPANS * LMAX)

// ---------------- scratch (static device globals; no allocation) -------------
__device__ float g_y[2 * MTOT * G4];            // xg for both dirs (~41 MB)
__device__ float g_wt[2 * H * G4];              // W_hh transposed: [dir][k][g]
__device__ float g_feats[NSPANS * EMB];         // [span][sum_f | sum_b]
__device__ int   g_rowSrc[MTOT];                // compacted valid row -> m
__device__ int   g_cnt;                         // number of valid rows
__device__ int   g_bCnt[LMAX + 1];              // span count per len (1..5)
__device__ int   g_bCur[LMAX + 1];              // scatter cursors per len
__device__ int   g_spanOrder[NSPANS];           // spans sorted by len desc

// ---------------- f32x2 packed helpers (sm_103a) -----------------------------
typedef unsigned long long ull;

__device__ __forceinline__ ull ffma2(ull a, ull b, ull c) {
    ull d;
    asm("fma.rn.f32x2 %0, %1, %2, %3;" : "=l"(d) : "l"(a), "l"(b), "l"(c));
    return d;
}
__device__ __forceinline__ ull pack2(float x) {
    ull r;
    asm("mov.b64 %0, {%1, %1};" : "=l"(r) : "f"(x));
    return r;
}
__device__ __forceinline__ ull packpair(float lo, float hi) {
    ull r;
    asm("mov.b64 %0, {%1, %2};" : "=l"(r) : "f"(lo), "f"(hi));
    return r;
}
__device__ __forceinline__ void unpack2(ull v, float& lo, float& hi) {
    asm("mov.b64 {%0, %1}, %2;" : "=f"(lo), "=f"(hi) : "l"(v));
}

// ---------------- kernel 0: transpose W_hh [800,200] -> [200,800] ------------
// Also zeroes the compaction counter + len buckets (runs first in stream).
__global__ void transpose_whh(const float* __restrict__ Wf,
                              const float* __restrict__ Wb) {
    if (blockIdx.x == 0 && blockIdx.y == 0 && blockIdx.z == 0 &&
        threadIdx.x == 0 && threadIdx.y == 0) {
        g_cnt = 0;
        for (int l = 0; l <= LMAX; l++) { g_bCnt[l] = 0; g_bCur[l] = 0; }
    }
    __shared__ float tile[32][33];
    int dir = blockIdx.z;
    const float* W = dir ? Wb : Wf;
    int k0 = blockIdx.x * 32;      // k (0..199)
    int g0 = blockIdx.y * 32;      // g (0..799)
    int tx = threadIdx.x, ty = threadIdx.y;   // 32 x 8
    #pragma unroll
    for (int i = 0; i < 32; i += 8) {
        int g = g0 + ty + i, k = k0 + tx;
        tile[ty + i][tx] = (g < G4 && k < H) ? W[g * H + k] : 0.f;
    }
    __syncthreads();
    #pragma unroll
    for (int i = 0; i < 32; i += 8) {
        int k = k0 + ty + i, g = g0 + tx;
        if (k < H && g < G4)
            g_wt[dir * (H * G4) + k * G4 + g] = tile[tx][ty + i];
    }
}

// ---------------- kernel 0b: valid-row list + len histogram ------------------
// Slot ORDER is atomic-dependent but downstream output is order-independent.
__global__ void compact_rows(const int* __restrict__ span_len) {
    int n = blockIdx.x * blockDim.x + threadIdx.x;
    if (n < NSPANS) {
        int len = span_len[n];
        int r = atomicAdd(&g_cnt, len);
        for (int l = 0; l < len; l++)
            g_rowSrc[r + l] = n * LMAX + l;
        atomicAdd(&g_bCnt[len], 1);
    }
}

// ---------------- kernel 0c: bucket offsets (descending len) -----------------
__global__ void bucket_offsets() {
    if (threadIdx.x == 0 && blockIdx.x == 0) {
        int off = 0;
        for (int len = LMAX; len >= 1; len--) {   // long spans first
            g_bCur[len] = off;
            off += g_bCnt[len];
        }
    }
}

// ---------------- kernel 0d: scatter spans into sorted order -----------------
__global__ void scatter_spans(const int* __restrict__ span_len) {
    int n = blockIdx.x * blockDim.x + threadIdx.x;
    if (n < NSPANS) {
        int len = span_len[n];
        int pos = atomicAdd(&g_bCur[len], 1);
        g_spanOrder[pos] = n;
    }
}

// ---------------- kernel 1: gathered input GEMM over valid rows --------------
// Double-buffered smem pipeline: stage tile i+1 while computing tile i.
#define BM 128
#define BN 64
#define BK 16
#define NKI (DIM / BK)

__global__ __launch_bounds__(256) void input_gemm(
    const float* __restrict__ hidden,
    const int*   __restrict__ tok_idx,
    const int*   __restrict__ span_batch,
    const float* __restrict__ Wf, const float* __restrict__ bihf, const float* __restrict__ bhhf,
    const float* __restrict__ Wb, const float* __restrict__ bihb, const float* __restrict__ bhhb)
{
    int Mv = g_cnt;                       // valid row count (set by compact_rows)
    int m0 = blockIdx.x * BM;
    if (m0 >= Mv) return;

    int dir = blockIdx.z;
    const float* W   = dir ? Wb   : Wf;
    const float* bih = dir ? bihb : bihf;
    const float* bhh = dir ? bhhb : bhhf;

    __shared__ __align__(16) float As[2][BK][BM + 4];
    __shared__ __align__(16) float Bs[2][BK][BN + 4];
    __shared__ int rowBase[BM];
    __shared__ int rowDst[BM];

    int tid = threadIdx.x;
    int g0 = blockIdx.y * BN;

    if (tid < BM) {
        int r = m0 + tid;
        int base = -1, msrc = -1;
        if (r < Mv) {
            msrc = g_rowSrc[r];
            int n = msrc / LMAX, l = msrc % LMAX;
            base = (span_batch[n] * SEQ + tok_idx[n * LMAX + l]) * DIM;
        }
        rowBase[tid] = base;
        rowDst[tid]  = msrc;
    }
    __syncthreads();

    const int aM0 = tid >> 2,         aKq0 = tid & 3;         // A load 0
    const int aM1 = (tid + 256) >> 2, aKq1 = tid & 3;         // A load 1
    const int bG  = tid >> 2,         bKq  = tid & 3;         // B load
    const int aBase0 = rowBase[aM0];
    const int aBase1 = rowBase[aM1];
    const int bOk = (g0 + bG) < G4;
    const float* bSrc = W + (size_t)(g0 + bG) * DIM + bKq * 4;

    auto stage = [&](int buf, int k0) {
        float4 v0 = make_float4(0.f, 0.f, 0.f, 0.f);
        float4 v1 = v0, vb = v0;
        if (aBase0 >= 0) v0 = *(const float4*)(hidden + aBase0 + k0 + aKq0 * 4);
        if (aBase1 >= 0) v1 = *(const float4*)(hidden + aBase1 + k0 + aKq1 * 4);
        if (bOk)         vb = *(const float4*)(bSrc + k0);
        As[buf][aKq0 * 4 + 0][aM0] = v0.x; As[buf][aKq0 * 4 + 1][aM0] = v0.y;
        As[buf][aKq0 * 4 + 2][aM0] = v0.z; As[buf][aKq0 * 4 + 3][aM0] = v0.w;
        As[buf][aKq1 * 4 + 0][aM1] = v1.x; As[buf][aKq1 * 4 + 1][aM1] = v1.y;
        As[buf][aKq1 * 4 + 2][aM1] = v1.z; As[buf][aKq1 * 4 + 3][aM1] = v1.w;
        Bs[buf][bKq * 4 + 0][bG] = vb.x; Bs[buf][bKq * 4 + 1][bG] = vb.y;
        Bs[buf][bKq * 4 + 2][bG] = vb.z; Bs[buf][bKq * 4 + 3][bG] = vb.w;
    };

    ull acc2[4][4];
    #pragma unroll
    for (int p = 0; p < 4; p++)
        #pragma unroll
        for (int j = 0; j < 4; j++) acc2[p][j] = 0ull;

    int ty = tid >> 4;   // 0..15 -> 8 rows each
    int tx = tid & 15;   // 0..15 -> 4 cols each

    stage(0, 0);
    __syncthreads();

    int cur = 0;
    for (int it = 0; it < NKI; it++) {
        if (it + 1 < NKI)
            stage(cur ^ 1, (it + 1) * BK);     // overlap with compute below

        #pragma unroll
        for (int k = 0; k < BK; k++) {
            ulonglong2 av0 = *(const ulonglong2*)(&As[cur][k][ty * 8]);
            ulonglong2 av1 = *(const ulonglong2*)(&As[cur][k][ty * 8 + 4]);
            ull ap[4] = {av0.x, av0.y, av1.x, av1.y};
            float4 bv = *(const float4*)(&Bs[cur][k][tx * 4]);
            ull bb[4] = {pack2(bv.x), pack2(bv.y), pack2(bv.z), pack2(bv.w)};
            #pragma unroll
            for (int p = 0; p < 4; p++)
                #pragma unroll
                for (int j = 0; j < 4; j++)
                    acc2[p][j] = ffma2(ap[p], bb[j], acc2[p][j]);
        }
        __syncthreads();
        cur ^= 1;
    }

    int gbase = g0 + tx * 4;
    if (gbase < G4) {
        float bias[4];
        #pragma unroll
        for (int j = 0; j < 4; j++) bias[j] = bih[gbase + j] + bhh[gbase + j];
        #pragma unroll
        for (int p = 0; p < 4; p++) {
            float lo[4], hi[4];
            #pragma unroll
            for (int j = 0; j < 4; j++) unpack2(acc2[p][j], lo[j], hi[j]);
            int d0 = rowDst[ty * 8 + 2 * p];
            int d1 = rowDst[ty * 8 + 2 * p + 1];
            if (d0 >= 0)
                *(float4*)(g_y + ((size_t)dir * MTOT + d0) * G4 + gbase) =
                    make_float4(lo[0] + bias[0], lo[1] + bias[1],
                                lo[2] + bias[2], lo[3] + bias[3]);
            if (d1 >= 0)
                *(float4*)(g_y + ((size_t)dir * MTOT + d1) * G4 + gbase) =
                    make_float4(hi[0] + bias[0], hi[1] + bias[1],
                                hi[2] + bias[2], hi[3] + bias[3]);
        }
    }
}

// ---------------- kernel 2: batched LSTM recurrence --------------------------
// GSP=4 spans (length-sorted) per block, 224 threads; thread j<200 owns unit j.
// Grid doubled vs GSP=8 -> ~4.3 blocks/SM, ~30 warps/SM for latency hiding
// (R4 showed occupancy was grid-limited at 14 warps/SM, issue=36%).
// t-loop runs only to the block's max span_len; k-loop skipped at t=0 (h=0).
// Steps with t >= len contribute nothing (sum masked; successors masked too),
// so clipped xg rows there are exact.
#define GSP 4

__global__ __launch_bounds__(224) void lstm_rec(
    const int* __restrict__ span_len)
{
    int dir = blockIdx.y;
    int s0  = blockIdx.x * GSP;
    int tid = threadIdx.x;

    __shared__ float hsm[H][GSP + 2];     // [unit][span], pitch 6 floats
    __shared__ int   len_s[GSP];
    __shared__ int   sid_s[GSP];

    if (tid < GSP) {
        int sid = g_spanOrder[s0 + tid];
        sid_s[tid] = sid;
        len_s[tid] = span_len[sid];
    }
    for (int i = tid; i < H * (GSP + 2); i += 224) ((float*)hsm)[i] = 0.f;
    __syncthreads();

    int tmax = 0;
    #pragma unroll
    for (int s = 0; s < GSP; s++) tmax = max(tmax, len_s[s]);

    const float* Wt = g_wt + (size_t)dir * (H * G4);
    const int j = tid;

    float c[GSP], sum[GSP], hn[GSP];
    #pragma unroll
    for (int s = 0; s < GSP; s++) { c[s] = 0.f; sum[s] = 0.f; hn[s] = 0.f; }

    for (int t = 0; t < tmax; t++) {
        if (tid < H) {
            // gate accumulators [gate][span-pair], init from xg (clipped row)
            ull a2[4][2];
            #pragma unroll
            for (int p = 0; p < 2; p++) {
                float v[2][4];
                #pragma unroll
                for (int half = 0; half < 2; half++) {
                    int s = 2 * p + half;
                    int len = len_s[s];
                    int tl = (dir == 0) ? min(t, len - 1) : max(len - 1 - t, 0);
                    const float* yr = g_y +
                        (((size_t)dir * NSPANS + sid_s[s]) * LMAX + tl) * G4;
                    #pragma unroll
                    for (int g = 0; g < 4; g++) v[half][g] = yr[g * H + j];
                }
                #pragma unroll
                for (int g = 0; g < 4; g++)
                    a2[g][p] = packpair(v[0][g], v[1][g]);
            }

            // h @ W_hh^T (K=200); skip entirely at t=0 (h == 0)
            if (t > 0) {
                #pragma unroll 4
                for (int k = 0; k < H; k++) {
                    const float* wr = Wt + (size_t)k * G4;
                    ull w[4];
                    #pragma unroll
                    for (int g = 0; g < 4; g++) w[g] = pack2(wr[g * H + j]);
                    ull hp[2];
                    #pragma unroll
                    for (int p = 0; p < 2; p++)
                        hp[p] = *(const ull*)&hsm[k][2 * p];
                    #pragma unroll
                    for (int g = 0; g < 4; g++)
                        #pragma unroll
                        for (int p = 0; p < 2; p++)
                            a2[g][p] = ffma2(hp[p], w[g], a2[g][p]);
                }
            }

            // nonlinearities (scalar per span)
            #pragma unroll
            for (int p = 0; p < 2; p++) {
                float ga[2][4];
                #pragma unroll
                for (int g = 0; g < 4; g++)
                    unpack2(a2[g][p], ga[0][g], ga[1][g]);
                #pragma unroll
                for (int half = 0; half < 2; half++) {
                    int s = 2 * p + half;
                    float ig = 1.f / (1.f + __expf(-ga[half][0]));
                    float fg = 1.f / (1.f + __expf(-ga[half][1]));
                    float gg = 1.f - 2.f / (1.f + __expf(2.f * ga[half][2]));  // tanh
                    float og = 1.f / (1.f + __expf(-ga[half][3]));
                    float cn = fg * c[s] + ig * gg;
                    c[s] = cn;
                    float hv = og * (1.f - 2.f / (1.f + __expf(2.f * cn)));
                    hn[s] = hv;
                    if (t < len_s[s]) sum[s] += hv;
                }
            }
        }
        __syncthreads();
        if (tid < H) {
            #pragma unroll
            for (int p = 0; p < 2; p++)
                *(float2*)&hsm[j][2 * p] = make_float2(hn[2 * p], hn[2 * p + 1]);
        }
        __syncthreads();
    }

    if (tid < H) {
        #pragma unroll
        for (int s = 0; s < GSP; s++)
            g_feats[(size_t)sid_s[s] * EMB + dir * H + j] = sum[s];
    }
}

// ---------------- kernel 3: logits = feats @ E^T -----------------------------
__global__ __launch_bounds__(256) void logits_kernel(
    const float* __restrict__ E, float* __restrict__ out)
{
    __shared__ float Es[NENT][EMB + 1];
    int tid = threadIdx.x;
    int s0  = blockIdx.x * 16;
    for (int i = tid; i < NENT * EMB; i += 256)
        Es[i / EMB][i % EMB] = E[i];
    __syncthreads();

    int sl = tid >> 4, e = tid & 15;
    const float* frow = g_feats + (size_t)(s0 + sl) * EMB;
    float acc = 0.f;
    #pragma unroll 4
    for (int k = 0; k < EMB; k++) acc += frow[k] * Es[e][k];
    out[(s0 + sl) * NENT + e] = acc;
}

// ---------------- launch -----------------------------------------------------
extern "C" void kernel_launch(void* const* d_in, const int* in_sizes, int n_in,
                              void* d_out, int out_size)
{
    const float* hidden = (const float*)d_in[0];
    const int*   tok    = (const int*)  d_in[1];
    const int*   slen   = (const int*)  d_in[2];
    const int*   sbatch = (const int*)  d_in[3];
    const float* Wihf   = (const float*)d_in[4];
    const float* Whhf   = (const float*)d_in[5];
    const float* bihf   = (const float*)d_in[6];
    const float* bhhf   = (const float*)d_in[7];
    const float* Wihb   = (const float*)d_in[8];
    const float* Whhb   = (const float*)d_in[9];
    const float* bihb   = (const float*)d_in[10];
    const float* bhhb   = (const float*)d_in[11];
    const float* E      = (const float*)d_in[12];
    float* out = (float*)d_out;

    transpose_whh<<<dim3(7, 25, 2), dim3(32, 8)>>>(Whhf, Whhb);   // zeroes counters
    compact_rows<<<(NSPANS + 255) / 256, 256>>>(slen);
    bucket_offsets<<<1, 1>>>();
    scatter_spans<<<(NSPANS + 255) / 256, 256>>>(slen);

    input_gemm<<<dim3(MTOT / BM, (G4 + BN - 1) / BN, 2), 256>>>(
        hidden, tok, sbatch, Wihf, bihf, bhhf, Wihb, bihb, bhhb);

    lstm_rec<<<dim3(NSPANS / GSP, 2), 224>>>(slen);

    logits_kernel<<<NSPANS / 16, 256>>>(E, out);
}